// round 8
// baseline (speedup 1.0000x reference)
#include <cuda_runtime.h>

#define Bn 64
#define Hn 512
#define Wn 512
#define HWn (Hn * Wn)
#define HW4 (HWn / 4)
#define CTAS_PER_BATCH 16
#define TILES_PER_CTA 8                 // tile = 4 rows; 8 tiles * 4 rows * 16 CTAs = 512 rows
#define GRID (Bn * CTAS_PER_BATCH)      // 1024 — single wave at 7 CTAs/SM

// Per-CTA partials — fully overwritten every launch before being read.
// Counter self-resets (elected warp zeroes it): deterministic across replays.
__device__ float    g_ps1[GRID];
__device__ float    g_ps2[GRID];
__device__ unsigned g_m1[GRID];     // bit (4*it + row_in_tile): label1 present
__device__ unsigned g_m2[GRID];     // same for label2
__device__ unsigned g_count[Bn];

__global__ void __launch_bounds__(256, 7) cdr_fused_kernel(const float* __restrict__ x,
                                                           float* __restrict__ out) {
    const int b    = blockIdx.x >> 4;           // batch
    const int c    = blockIdx.x & 15;           // CTA index within batch
    const int tid  = threadIdx.x;
    const int rsel = tid >> 7;                  // 0: rows {4g,4g+1}, 1: rows {4g+2,4g+3}
    const int c4   = tid & 127;                 // float4 column index

    const float4* p = (const float4*)x;
    const size_t batch_base = ((size_t)b * 3 * HWn) >> 2;

    float s1 = 0.f, s2 = 0.f;
    unsigned m1 = 0, m2 = 0;

#pragma unroll
    for (int it = 0; it < TILES_PER_CTA; it++) {
        const int g   = c + 16 * it;            // row-group (4 rows) within batch
        const int rA  = g * 4 + rsel * 2;       // first of this thread's two rows
        const size_t base = batch_base + (((size_t)rA * Wn) >> 2) + (size_t)c4;

        // 6 coalesced LDG.128 (front-batched by ptxas at this reg budget)
        float4 v0a = p[base];
        float4 v1a = p[base + HW4];
        float4 v2a = p[base + 2 * HW4];
        float4 v0b = p[base + 128];             // row rA+1
        float4 v1b = p[base + HW4 + 128];
        float4 v2b = p[base + 2 * HW4 + 128];

        const int bitA = it * 4 + rsel * 2;
        bool anyA1 = false, anyA2 = false, anyB1 = false, anyB2 = false;

        const float* f0 = (const float*)&v0a;
        const float* f1 = (const float*)&v1a;
        const float* f2 = (const float*)&v2a;
        const float* h0 = (const float*)&v0b;
        const float* h1 = (const float*)&v1b;
        const float* h2 = (const float*)&v2b;

#pragma unroll
        for (int k = 0; k < 4; k++) {
            float a0 = f0[k], a1 = f1[k], a2 = f2[k];
            float m01 = fmaxf(a0, a1);
            bool  l2  = a2 > m01;
            bool  l1  = (a1 > a0) && !l2;
            anyA1 |= l1;
            anyA2 |= l2;
            float e0  = __expf(a0 - a1);
            float e2  = __expf(a2 - a1);
            float inv = __fdividef(1.0f, e0 + 1.0f + e2);
            s1 += inv;        // p(cup)
            s2 += e2 * inv;   // p(disc)
        }
#pragma unroll
        for (int k = 0; k < 4; k++) {
            float a0 = h0[k], a1 = h1[k], a2 = h2[k];
            float m01 = fmaxf(a0, a1);
            bool  l2  = a2 > m01;
            bool  l1  = (a1 > a0) && !l2;
            anyB1 |= l1;
            anyB2 |= l2;
            float e0  = __expf(a0 - a1);
            float e2  = __expf(a2 - a1);
            float inv = __fdividef(1.0f, e0 + 1.0f + e2);
            s1 += inv;
            s2 += e2 * inv;
        }
        if (anyA1) m1 |= 1u << bitA;
        if (anyA2) m2 |= 1u << bitA;
        if (anyB1) m1 |= 1u << (bitA + 1);
        if (anyB2) m2 |= 1u << (bitA + 1);
    }

    // ---- once-per-CTA deterministic reduction ----
#pragma unroll
    for (int o = 16; o > 0; o >>= 1) {
        s1 += __shfl_xor_sync(0xFFFFFFFFu, s1, o);
        s2 += __shfl_xor_sync(0xFFFFFFFFu, s2, o);
        m1 |= __shfl_xor_sync(0xFFFFFFFFu, m1, o);
        m2 |= __shfl_xor_sync(0xFFFFFFFFu, m2, o);
    }

    __shared__ float    sw1[8], sw2[8];
    __shared__ unsigned sm1[8], sm2[8];
    const int wid = tid >> 5, lid = tid & 31;
    if (lid == 0) { sw1[wid] = s1; sw2[wid] = s2; sm1[wid] = m1; sm2[wid] = m2; }
    __syncthreads();
    if (wid != 0) return;   // 7 of 8 warps retire

    float    pv1 = (lid < 8) ? sw1[lid] : 0.f;
    float    pv2 = (lid < 8) ? sw2[lid] : 0.f;
    unsigned pm1 = (lid < 8) ? sm1[lid] : 0u;
    unsigned pm2 = (lid < 8) ? sm2[lid] : 0u;
#pragma unroll
    for (int o = 4; o > 0; o >>= 1) {
        pv1 += __shfl_xor_sync(0xFFFFFFFFu, pv1, o);
        pv2 += __shfl_xor_sync(0xFFFFFFFFu, pv2, o);
        pm1 |= __shfl_xor_sync(0xFFFFFFFFu, pm1, o);
        pm2 |= __shfl_xor_sync(0xFFFFFFFFu, pm2, o);
    }

    int lastFlag = 0;
    if (lid == 0) {
        g_ps1[blockIdx.x] = pv1;
        g_ps2[blockIdx.x] = pv2;
        g_m1[blockIdx.x]  = pm1;
        g_m2[blockIdx.x]  = pm2;
        __threadfence();
        lastFlag = (atomicAdd(&g_count[b], 1u) == CTAS_PER_BATCH - 1);
    }
    lastFlag = __shfl_sync(0xFFFFFFFFu, lastFlag, 0);
    if (!lastFlag) return;

    // ---- elected CTA's warp 0 finalizes batch b: 16 partials, one per lane ----
    float t1 = 0.f, t2 = 0.f;
    unsigned fm1 = 0, fm2 = 0;
    if (lid < CTAS_PER_BATCH) {
        const int idx = b * CTAS_PER_BATCH + lid;
        t1  = __ldcg(&g_ps1[idx]);
        t2  = __ldcg(&g_ps2[idx]);
        fm1 = __ldcg(&g_m1[idx]);
        fm2 = __ldcg(&g_m2[idx]);
    }
    // decode row extents per lane (lane = CTA index c within batch)
    int mn1 = Hn, mx1 = -1, mn2 = Hn, mx2 = -1;
#pragma unroll
    for (int it = 0; it < TILES_PER_CTA; it++) {
        const int rowbase = (lid + 16 * it) * 4;
        unsigned n1 = (fm1 >> (4 * it)) & 0xFu;
        unsigned n2 = (fm2 >> (4 * it)) & 0xFu;
        if (n1) {
            mn1 = min(mn1, rowbase + (__ffs(n1) - 1));
            mx1 = max(mx1, rowbase + (31 - __clz(n1)));
        }
        if (n2) {
            mn2 = min(mn2, rowbase + (__ffs(n2) - 1));
            mx2 = max(mx2, rowbase + (31 - __clz(n2)));
        }
    }
#pragma unroll
    for (int o = 16; o > 0; o >>= 1) {
        t1  += __shfl_xor_sync(0xFFFFFFFFu, t1, o);
        t2  += __shfl_xor_sync(0xFFFFFFFFu, t2, o);
        mn1  = min(mn1, __shfl_xor_sync(0xFFFFFFFFu, mn1, o));
        mx1  = max(mx1, __shfl_xor_sync(0xFFFFFFFFu, mx1, o));
        mn2  = min(mn2, __shfl_xor_sync(0xFFFFFFFFu, mn2, o));
        mx2  = max(mx2, __shfl_xor_sync(0xFFFFFFFFu, mx2, o));
    }

    if (lid == 0) {
        const float inv_hw = 1.0f / (float)HWn;
        float cup_mean  = t1 * inv_hw;
        float disc_mean = t2 * inv_hw;
        float hcup  = (mx1 >= 0) ? (float)(mx1 - mn1) : 0.0f;
        float hdisc = (mx2 >= 0) ? (float)(mx2 - mn2) : 0.0f;
        float cdr = hcup / (hdisc + 1e-6f);
        out[b * 5 + 0] = cdr;
        out[b * 5 + 1] = disc_mean;
        out[b * 5 + 2] = cup_mean;
        out[b * 5 + 3] = disc_mean;
        out[b * 5 + 4] = cup_mean;
        g_count[b] = 0;   // self-reset: deterministic across graph replays
    }
}

extern "C" void kernel_launch(void* const* d_in, const int* in_sizes, int n_in,
                              void* d_out, int out_size) {
    const float* x = (const float*)d_in[0];
    float* out = (float*)d_out;
    (void)in_sizes; (void)n_in; (void)out_size;

    cdr_fused_kernel<<<GRID, 256>>>(x, out);
}